// round 1
// baseline (speedup 1.0000x reference)
#include <cuda_runtime.h>
#include <math.h>
#include <stdint.h>

// ---------------------------------------------------------------------------
// GCN encoder: 3x (GCNConv -> ReLU -> (x + x@W^T) -> ReLU)
// dims: 128 -> 128 -> 64 -> 128, N=100000 nodes, E=1.6M edges
// ---------------------------------------------------------------------------

#define NMAX 100000
#define DMAX 128

// Scratch (statically allocated; no cudaMalloc allowed)
__device__ float g_dinv[NMAX];
__device__ float g_bufA[(size_t)NMAX * DMAX];
__device__ float g_bufB[(size_t)NMAX * DMAX];

// ---------------------------- degree / norm --------------------------------

__global__ void deg_init_kernel(float* __restrict__ dinv, int n) {
    int i = blockIdx.x * 256 + threadIdx.x;
    if (i < n) dinv[i] = 1.0f;  // self-loop contributes 1
}

__global__ void deg_count_kernel(const int* __restrict__ dst, float* __restrict__ dinv, int E) {
    int e = blockIdx.x * 256 + threadIdx.x;
    if (e < E) atomicAdd(&dinv[dst[e]], 1.0f);
}

__global__ void deg_fin_kernel(float* __restrict__ dinv, int n) {
    int i = blockIdx.x * 256 + threadIdx.x;
    if (i < n) dinv[i] = rsqrtf(dinv[i]);  // deg >= 1 always (self-loop)
}

// ------------------- bias + self-loop init of aggregation ------------------
// out[i, :] = b + h[i, :] * dinv[i]^2      (DQ = D/4)

__global__ void init_self_kernel(const float* __restrict__ h,
                                 const float* __restrict__ dinv,
                                 const float* __restrict__ b,
                                 float* __restrict__ out,
                                 int n, int dq) {
    int idx = blockIdx.x * 256 + threadIdx.x;
    if (idx >= n * dq) return;
    int i = idx / dq;
    int c = idx - i * dq;
    float di = dinv[i];
    float s = di * di;
    float4 hv = ((const float4*)h)[idx];
    float4 bv = ((const float4*)b)[c];
    float4 o;
    o.x = bv.x + hv.x * s;
    o.y = bv.y + hv.y * s;
    o.z = bv.z + hv.z * s;
    o.w = bv.w + hv.w * s;
    ((float4*)out)[idx] = o;
}

// ---------------------------- edge aggregation -----------------------------
// out[dst] += h[src] * dinv[src]*dinv[dst]

__device__ __forceinline__ void red_add_v4(float* p, float4 m) {
    asm volatile("red.global.v4.f32.add [%0], {%1,%2,%3,%4};"
                 :: "l"(p), "f"(m.x), "f"(m.y), "f"(m.z), "f"(m.w)
                 : "memory");
}

// D = 128: one warp per edge, lane covers 4 columns
__global__ void edge_agg128_kernel(const int* __restrict__ src,
                                   const int* __restrict__ dst,
                                   const float* __restrict__ dinv,
                                   const float* __restrict__ h,
                                   float* __restrict__ out, int E) {
    int t = blockIdx.x * 256 + threadIdx.x;
    int e = t >> 5;
    int lane = t & 31;
    if (e >= E) return;
    int s = __ldg(&src[e]);
    int d = __ldg(&dst[e]);
    float norm = __ldg(&dinv[s]) * __ldg(&dinv[d]);
    float4 v = *(const float4*)(h + (size_t)s * 128 + lane * 4);
    float4 m;
    m.x = v.x * norm; m.y = v.y * norm; m.z = v.z * norm; m.w = v.w * norm;
    red_add_v4(out + (size_t)d * 128 + lane * 4, m);
}

// D = 64: half-warp per edge
__global__ void edge_agg64_kernel(const int* __restrict__ src,
                                  const int* __restrict__ dst,
                                  const float* __restrict__ dinv,
                                  const float* __restrict__ h,
                                  float* __restrict__ out, int E) {
    int t = blockIdx.x * 256 + threadIdx.x;
    int e = t >> 4;
    int lane = t & 15;
    if (e >= E) return;
    int s = __ldg(&src[e]);
    int d = __ldg(&dst[e]);
    float norm = __ldg(&dinv[s]) * __ldg(&dinv[d]);
    float4 v = *(const float4*)(h + (size_t)s * 64 + lane * 4);
    float4 m;
    m.x = v.x * norm; m.y = v.y * norm; m.z = v.z * norm; m.w = v.w * norm;
    red_add_v4(out + (size_t)d * 64 + lane * 4, m);
}

// --------------------------------- GEMM ------------------------------------
// C[n, M] = act(A[n, K]) @ Wmat     (Wmat: [K,M] row-major, or [M,K] if TRANS)
// Optional: RELU_IN on A, RESID adds act(A) (requires K==M), RELU_OUT on C.
// Block: 256 threads -> 64 rows x M cols tile; full W resident in SMEM.

template <int K, int M, bool TRANS, bool RELU_IN, bool RESID, bool RELU_OUT>
__global__ __launch_bounds__(256) void gemm_kernel(const float* __restrict__ A,
                                                   const float* __restrict__ W,
                                                   float* __restrict__ C, int n) {
    constexpr int AS = K + 4;      // padded A stride (bank-conflict avoidance)
    constexpr int TN = M / 16;     // cols per thread (8 for M=128, 4 for M=64)
    extern __shared__ float sm[];
    float* As = sm;                // [64][AS]
    float* Ws = sm + 64 * AS;      // [K][M]

    int tid = threadIdx.x;
    int row0 = blockIdx.x * 64;

    // --- stage A (with optional relu) ---
    #pragma unroll 2
    for (int i = tid; i < 64 * (K / 4); i += 256) {
        int r = i / (K / 4);
        int c4 = i - r * (K / 4);
        float4 v = make_float4(0.f, 0.f, 0.f, 0.f);
        if (row0 + r < n) v = ((const float4*)A)[(size_t)(row0 + r) * (K / 4) + c4];
        if (RELU_IN) {
            v.x = fmaxf(v.x, 0.f); v.y = fmaxf(v.y, 0.f);
            v.z = fmaxf(v.z, 0.f); v.w = fmaxf(v.w, 0.f);
        }
        float* p = As + r * AS + c4 * 4;
        p[0] = v.x; p[1] = v.y; p[2] = v.z; p[3] = v.w;
    }

    // --- stage W ---
    if (!TRANS) {
        #pragma unroll 2
        for (int i = tid; i < K * (M / 4); i += 256) {
            int k = i / (M / 4);
            int m4 = i - k * (M / 4);
            float4 v = ((const float4*)W)[i];
            ((float4*)(Ws + k * M))[m4] = v;
        }
    } else {
        // W is [M,K] row-major; Ws[k][m] = W[m*K + k]
        #pragma unroll 2
        for (int i = tid; i < M * (K / 4); i += 256) {
            int m = i / (K / 4);
            int k4 = i - m * (K / 4);
            float4 v = ((const float4*)W)[i];
            Ws[(k4 * 4 + 0) * M + m] = v.x;
            Ws[(k4 * 4 + 1) * M + m] = v.y;
            Ws[(k4 * 4 + 2) * M + m] = v.z;
            Ws[(k4 * 4 + 3) * M + m] = v.w;
        }
    }
    __syncthreads();

    int ty = tid >> 4;         // 0..15  -> 4 rows each
    int tx = tid & 15;         // 0..15  -> TN cols each
    const float* arow = As + (ty * 4) * AS;
    const float* wcol = Ws + tx * TN;

    float acc[4][TN];
    #pragma unroll
    for (int r = 0; r < 4; ++r)
        #pragma unroll
        for (int j = 0; j < TN; ++j) acc[r][j] = 0.f;

    #pragma unroll 8
    for (int k = 0; k < K; ++k) {
        float a0 = arow[k];
        float a1 = arow[AS + k];
        float a2 = arow[2 * AS + k];
        float a3 = arow[3 * AS + k];
        #pragma unroll
        for (int j = 0; j < TN; ++j) {
            float w = wcol[k * M + j];
            acc[0][j] += a0 * w;
            acc[1][j] += a1 * w;
            acc[2][j] += a2 * w;
            acc[3][j] += a3 * w;
        }
    }

    // --- epilogue ---
    #pragma unroll
    for (int r = 0; r < 4; ++r) {
        int gr = row0 + ty * 4 + r;
        if (gr >= n) continue;
        #pragma unroll
        for (int j = 0; j < TN; j += 4) {
            float4 o;
            float v0 = acc[r][j + 0], v1 = acc[r][j + 1], v2 = acc[r][j + 2], v3 = acc[r][j + 3];
            if (RESID) {  // only instantiated when K == M
                const float* ar = As + (ty * 4 + r) * AS + tx * TN + j;
                v0 += ar[0]; v1 += ar[1]; v2 += ar[2]; v3 += ar[3];
            }
            if (RELU_OUT) {
                v0 = fmaxf(v0, 0.f); v1 = fmaxf(v1, 0.f);
                v2 = fmaxf(v2, 0.f); v3 = fmaxf(v3, 0.f);
            }
            o.x = v0; o.y = v1; o.z = v2; o.w = v3;
            *((float4*)(C + (size_t)gr * M + tx * TN + j)) = o;
        }
    }
}

template <int K, int M, bool TRANS, bool RELU_IN, bool RESID, bool RELU_OUT>
static void launch_gemm(const float* A, const float* W, float* C, int n) {
    constexpr int SMEM = (64 * (K + 4) + K * M) * 4;
    if (SMEM > 48 * 1024) {
        cudaFuncSetAttribute(gemm_kernel<K, M, TRANS, RELU_IN, RESID, RELU_OUT>,
                             cudaFuncAttributeMaxDynamicSharedMemorySize, SMEM);
    }
    gemm_kernel<K, M, TRANS, RELU_IN, RESID, RELU_OUT><<<(n + 63) / 64, 256, SMEM>>>(A, W, C, n);
}

// --------------------------------- driver ----------------------------------

extern "C" void kernel_launch(void* const* d_in, const int* in_sizes, int n_in,
                              void* d_out, int out_size) {
    const float* x     = (const float*)d_in[0];
    const int*   ei    = (const int*)d_in[1];
    const float* g1w   = (const float*)d_in[2];
    const float* g1b   = (const float*)d_in[3];
    const float* fc2w  = (const float*)d_in[4];
    const float* g3w   = (const float*)d_in[5];
    const float* g3b   = (const float*)d_in[6];
    const float* fc4w  = (const float*)d_in[7];
    const float* g5w   = (const float*)d_in[8];
    const float* g5b   = (const float*)d_in[9];
    const float* fc6w  = (const float*)d_in[10];

    int n = in_sizes[0] / 128;
    int E = in_sizes[1] / 2;
    const int* src = ei;
    const int* dst = ei + E;

    float *dinv, *bA, *bB;
    cudaGetSymbolAddress((void**)&dinv, g_dinv);
    cudaGetSymbolAddress((void**)&bA, g_bufA);
    cudaGetSymbolAddress((void**)&bB, g_bufB);

    // normalization: dinv = rsqrt(1 + in-degree)
    deg_init_kernel<<<(n + 255) / 256, 256>>>(dinv, n);
    deg_count_kernel<<<(E + 255) / 256, 256>>>(dst, dinv, E);
    deg_fin_kernel<<<(n + 255) / 256, 256>>>(dinv, n);

    // ---- layer 1: GCN(128->128) + ReLU + residual FC + ReLU ----
    launch_gemm<128, 128, false, false, false, false>(x, g1w, bA, n);      // h1 = x @ W1
    init_self_kernel<<<(n * 32 + 255) / 256, 256>>>(bA, dinv, g1b, bB, n, 32);
    edge_agg128_kernel<<<(E * 32 + 255) / 256, 256>>>(src, dst, dinv, bA, bB, E);
    launch_gemm<128, 128, true, true, true, true>(bB, fc2w, bA, n);        // z1'

    // ---- layer 2: GCN(128->64) + ReLU + residual FC + ReLU ----
    launch_gemm<128, 64, false, false, false, false>(bA, g3w, bB, n);      // h2
    init_self_kernel<<<(n * 16 + 255) / 256, 256>>>(bB, dinv, g3b, bA, n, 16);
    edge_agg64_kernel<<<(E * 16 + 255) / 256, 256>>>(src, dst, dinv, bB, bA, E);
    launch_gemm<64, 64, true, true, true, true>(bA, fc4w, bB, n);          // z2'

    // ---- layer 3: GCN(64->128) + ReLU + residual FC + ReLU ----
    launch_gemm<64, 128, false, false, false, false>(bB, g5w, bA, n);      // h3
    init_self_kernel<<<(n * 32 + 255) / 256, 256>>>(bA, dinv, g5b, bB, n, 32);
    edge_agg128_kernel<<<(E * 32 + 255) / 256, 256>>>(src, dst, dinv, bA, bB, E);
    launch_gemm<128, 128, true, true, true, true>(bB, fc6w, (float*)d_out, n);
}

// round 3
// speedup vs baseline: 1.4593x; 1.4593x over previous
#include <cuda_runtime.h>
#include <cuda_bf16.h>
#include <mma.h>
#include <math.h>
#include <stdint.h>

using namespace nvcuda;

// ---------------------------------------------------------------------------
// GCN encoder on GB300: bf16x3 WMMA (HMMA) GEMMs + edge aggregation
// ---------------------------------------------------------------------------

#define NMAX 100000

__device__ float g_dinv[NMAX];
__device__ float g_bufA[(size_t)NMAX * 128];
__device__ float g_bufB[(size_t)NMAX * 128];
__device__ float g_bufC[(size_t)NMAX * 128];

// ---------------------------- degree / norm --------------------------------

__global__ void deg_init_kernel(float* __restrict__ dinv, int n) {
    int i = blockIdx.x * 256 + threadIdx.x;
    if (i < n) dinv[i] = 1.0f;
}

__global__ void deg_count_kernel(const int* __restrict__ dst, float* __restrict__ dinv, int E) {
    int e = blockIdx.x * 256 + threadIdx.x;
    if (e < E) atomicAdd(&dinv[dst[e]], 1.0f);
}

__global__ void deg_fin_kernel(float* __restrict__ dinv, int n) {
    int i = blockIdx.x * 256 + threadIdx.x;
    if (i < n) dinv[i] = rsqrtf(dinv[i]);
}

// ---------------------------- edge aggregation -----------------------------

__device__ __forceinline__ void red_add_v4(float* p, float4 m) {
    asm volatile("red.global.v4.f32.add [%0], {%1,%2,%3,%4};"
                 :: "l"(p), "f"(m.x), "f"(m.y), "f"(m.z), "f"(m.w)
                 : "memory");
}

__global__ void edge_agg128_kernel(const int* __restrict__ src,
                                   const int* __restrict__ dst,
                                   const float* __restrict__ dinv,
                                   const float* __restrict__ h,
                                   float* __restrict__ out, int E) {
    int t = blockIdx.x * 256 + threadIdx.x;
    int e = t >> 5;
    int lane = t & 31;
    if (e >= E) return;
    int s = __ldg(&src[e]);
    int d = __ldg(&dst[e]);
    float norm = __ldg(&dinv[s]) * __ldg(&dinv[d]);
    float4 v = *(const float4*)(h + (size_t)s * 128 + lane * 4);
    float4 m;
    m.x = v.x * norm; m.y = v.y * norm; m.z = v.z * norm; m.w = v.w * norm;
    red_add_v4(out + (size_t)d * 128 + lane * 4, m);
}

__global__ void edge_agg64_kernel(const int* __restrict__ src,
                                  const int* __restrict__ dst,
                                  const float* __restrict__ dinv,
                                  const float* __restrict__ h,
                                  float* __restrict__ out, int E) {
    int t = blockIdx.x * 256 + threadIdx.x;
    int e = t >> 4;
    int lane = t & 15;
    if (e >= E) return;
    int s = __ldg(&src[e]);
    int d = __ldg(&dst[e]);
    float norm = __ldg(&dinv[s]) * __ldg(&dinv[d]);
    float4 v = *(const float4*)(h + (size_t)s * 64 + lane * 4);
    float4 m;
    m.x = v.x * norm; m.y = v.y * norm; m.z = v.z * norm; m.w = v.w * norm;
    red_add_v4(out + (size_t)d * 64 + lane * 4, m);
}

// ------------------------------- WMMA GEMM ---------------------------------
// C[n, N] = act(A[n, K]) @ B via bf16 split-3 (hi*hi + hi*lo + lo*hi).
// B[k][n]: TRANSB ? W[k*N + n]  (W is [K][N], GCN weight, row_major frag)
//                 : W[n*K + k]  (W is [N][K], nn.Linear weight, col_major frag)
// EPI: 0 = relu(reluA + d) -> C                         (needs K == N)
//      1 = d -> C ; bias + d*dinv^2 -> C2
//      2 = relu(reluA + d) -> C ; same * dinv^2 -> C2   (needs K == N)
//      3 = d + bias -> C
// Tile: 64 rows x N cols, 8 warps (2 M x 4 N), full K resident.

__device__ __forceinline__ uint32_t pack_bf2(float a, float b) {
    __nv_bfloat162 p;
    p.x = __float2bfloat16(a);
    p.y = __float2bfloat16(b);
    return *reinterpret_cast<uint32_t*>(&p);
}

template <int K, int N, bool TRANSB, bool RELU_IN, int EPI>
__global__ __launch_bounds__(256) void wmma_gemm_kernel(
    const float* __restrict__ A, const float* __restrict__ W,
    float* __restrict__ C, float* __restrict__ C2,
    const float* __restrict__ bias, const float* __restrict__ dinv, int n) {
    constexpr int LDA = K + 8;                     // bf16 elems
    constexpr int LDB = TRANSB ? (N + 8) : (K + 8);
    constexpr int LDC = N + 8;                     // f32 elems
    constexpr int SA = 64 * LDA * 2;               // bytes, one of hi/lo
    constexpr int SB = (TRANSB ? K * (N + 8) : N * (K + 8)) * 2;
    constexpr int B_HI_OFF = 2 * SA;
    constexpr int B_LO_OFF = 2 * SA + SB;
    constexpr int C_OFF = 2 * SA + 2 * SB;
    constexpr int WN = N / 64;                     // n-tiles per warp (2 or 1)

    extern __shared__ __align__(16) char smem[];
    __nv_bfloat16* Ah = (__nv_bfloat16*)smem;
    __nv_bfloat16* Al = (__nv_bfloat16*)(smem + SA);
    __nv_bfloat16* Bh = (__nv_bfloat16*)(smem + B_HI_OFF);
    __nv_bfloat16* Bl = (__nv_bfloat16*)(smem + B_LO_OFF);
    float* Cs = (float*)(smem + C_OFF);

    const int tid = threadIdx.x;
    const int w = tid >> 5;
    const int row0 = blockIdx.x * 64;

    // ---- stage A (relu optional, hi/lo split) ----
    constexpr int KQ = K / 4;
    for (int idx = tid; idx < 64 * KQ; idx += 256) {
        int r = idx / KQ;
        int k0 = (idx - r * KQ) * 4;
        float4 v = make_float4(0.f, 0.f, 0.f, 0.f);
        if (row0 + r < n) v = *(const float4*)(A + (size_t)(row0 + r) * K + k0);
        if (RELU_IN) {
            v.x = fmaxf(v.x, 0.f); v.y = fmaxf(v.y, 0.f);
            v.z = fmaxf(v.z, 0.f); v.w = fmaxf(v.w, 0.f);
        }
        __nv_bfloat16 h0 = __float2bfloat16(v.x), h1 = __float2bfloat16(v.y);
        __nv_bfloat16 h2 = __float2bfloat16(v.z), h3 = __float2bfloat16(v.w);
        float l0 = v.x - __bfloat162float(h0), l1 = v.y - __bfloat162float(h1);
        float l2 = v.z - __bfloat162float(h2), l3 = v.w - __bfloat162float(h3);
        __nv_bfloat162 hh0; hh0.x = h0; hh0.y = h1;
        __nv_bfloat162 hh1; hh1.x = h2; hh1.y = h3;
        *(uint2*)(Ah + r * LDA + k0) =
            make_uint2(*(uint32_t*)&hh0, *(uint32_t*)&hh1);
        *(uint2*)(Al + r * LDA + k0) = make_uint2(pack_bf2(l0, l1), pack_bf2(l2, l3));
    }

    // ---- stage B (hi/lo split, native layout) ----
    {
        constexpr int RB = TRANSB ? K : N;   // rows of source W
        constexpr int CB = TRANSB ? N : K;   // cols of source W
        constexpr int CQ = CB / 4;
        for (int idx = tid; idx < RB * CQ; idx += 256) {
            int r = idx / CQ;
            int c0 = (idx - r * CQ) * 4;
            float4 v = *(const float4*)(W + (size_t)r * CB + c0);
            __nv_bfloat16 h0 = __float2bfloat16(v.x), h1 = __float2bfloat16(v.y);
            __nv_bfloat16 h2 = __float2bfloat16(v.z), h3 = __float2bfloat16(v.w);
            float l0 = v.x - __bfloat162float(h0), l1 = v.y - __bfloat162float(h1);
            float l2 = v.z - __bfloat162float(h2), l3 = v.w - __bfloat162float(h3);
            __nv_bfloat162 hh0; hh0.x = h0; hh0.y = h1;
            __nv_bfloat162 hh1; hh1.x = h2; hh1.y = h3;
            *(uint2*)(Bh + r * LDB + c0) =
                make_uint2(*(uint32_t*)&hh0, *(uint32_t*)&hh1);
            *(uint2*)(Bl + r * LDB + c0) = make_uint2(pack_bf2(l0, l1), pack_bf2(l2, l3));
        }
    }
    __syncthreads();

    // ---- WMMA mainloop ----
    const int wm = w >> 2;      // 0..1 (32 rows each)
    const int wn = w & 3;       // 0..3 (N/4 cols each)

    wmma::fragment<wmma::accumulator, 16, 16, 16, float> acc[2][WN];
#pragma unroll
    for (int t = 0; t < 2; t++)
#pragma unroll
        for (int j = 0; j < WN; j++) wmma::fill_fragment(acc[t][j], 0.f);

#pragma unroll
    for (int kk = 0; kk < K / 16; kk++) {
        wmma::fragment<wmma::matrix_a, 16, 16, 16, __nv_bfloat16, wmma::row_major> a_hi[2], a_lo[2];
#pragma unroll
        for (int t = 0; t < 2; t++) {
            const __nv_bfloat16* pa = Ah + (wm * 32 + t * 16) * LDA + kk * 16;
            const __nv_bfloat16* pl = Al + (wm * 32 + t * 16) * LDA + kk * 16;
            wmma::load_matrix_sync(a_hi[t], pa, LDA);
            wmma::load_matrix_sync(a_lo[t], pl, LDA);
        }
#pragma unroll
        for (int j = 0; j < WN; j++) {
            int n0 = wn * (N / 4) + j * 16;
            if (TRANSB) {
                wmma::fragment<wmma::matrix_b, 16, 16, 16, __nv_bfloat16, wmma::row_major> b_hi, b_lo;
                wmma::load_matrix_sync(b_hi, Bh + kk * 16 * LDB + n0, LDB);
                wmma::load_matrix_sync(b_lo, Bl + kk * 16 * LDB + n0, LDB);
#pragma unroll
                for (int t = 0; t < 2; t++) {
                    wmma::mma_sync(acc[t][j], a_hi[t], b_hi, acc[t][j]);
                    wmma::mma_sync(acc[t][j], a_hi[t], b_lo, acc[t][j]);
                    wmma::mma_sync(acc[t][j], a_lo[t], b_hi, acc[t][j]);
                }
            } else {
                wmma::fragment<wmma::matrix_b, 16, 16, 16, __nv_bfloat16, wmma::col_major> b_hi, b_lo;
                wmma::load_matrix_sync(b_hi, Bh + n0 * LDB + kk * 16, LDB);
                wmma::load_matrix_sync(b_lo, Bl + n0 * LDB + kk * 16, LDB);
#pragma unroll
                for (int t = 0; t < 2; t++) {
                    wmma::mma_sync(acc[t][j], a_hi[t], b_hi, acc[t][j]);
                    wmma::mma_sync(acc[t][j], a_hi[t], b_lo, acc[t][j]);
                    wmma::mma_sync(acc[t][j], a_lo[t], b_hi, acc[t][j]);
                }
            }
        }
    }

    // ---- store accumulators to SMEM C tile ----
#pragma unroll
    for (int t = 0; t < 2; t++)
#pragma unroll
        for (int j = 0; j < WN; j++)
            wmma::store_matrix_sync(Cs + (wm * 32 + t * 16) * LDC + wn * (N / 4) + j * 16,
                                    acc[t][j], LDC, wmma::mem_row_major);
    __syncthreads();

    // ---- epilogue ----
    constexpr int NQ = N / 4;
    for (int idx = tid; idx < 64 * NQ; idx += 256) {
        int r = idx / NQ;
        int c0 = (idx - r * NQ) * 4;
        int grow = row0 + r;
        if (grow >= n) continue;
        float s = 0.f;
        if (EPI == 1 || EPI == 2) {
            float dv = __ldg(&dinv[grow]);
            s = dv * dv;
        }
        float4 o, o2;
#pragma unroll
        for (int jj = 0; jj < 4; jj++) {
            int col = c0 + jj;
            float d = Cs[r * LDC + col];
            float val, val2 = 0.f;
            if (EPI == 0 || EPI == 2) {
                float ah = __bfloat162float(Ah[r * LDA + col]);
                float al = __bfloat162float(Al[r * LDA + col]);
                val = fmaxf(ah + al + d, 0.f);
                if (EPI == 2) val2 = val * s;
            } else if (EPI == 1) {
                val = d;
                val2 = __ldg(&bias[col]) + d * s;
            } else {
                val = d + __ldg(&bias[col]);
            }
            (&o.x)[jj] = val;
            (&o2.x)[jj] = val2;
        }
        *(float4*)(C + (size_t)grow * N + c0) = o;
        if (EPI == 1 || EPI == 2) *(float4*)(C2 + (size_t)grow * N + c0) = o2;
    }
}

template <int K, int N, bool TRANSB, bool RELU_IN, int EPI>
static void launch_wmma(const float* A, const float* W, float* C, float* C2,
                        const float* bias, const float* dinv, int n) {
    constexpr int SA = 64 * (K + 8) * 2;
    constexpr int SB = (TRANSB ? K * (N + 8) : N * (K + 8)) * 2;
    constexpr int SMEM = 2 * SA + 2 * SB + 64 * (N + 8) * 4;
    auto kfn = wmma_gemm_kernel<K, N, TRANSB, RELU_IN, EPI>;
    if (SMEM > 48 * 1024)
        cudaFuncSetAttribute(kfn, cudaFuncAttributeMaxDynamicSharedMemorySize, SMEM);
    kfn<<<(n + 63) / 64, 256, SMEM>>>(A, W, C, C2, bias, dinv, n);
}

// --------------------------------- driver ----------------------------------

extern "C" void kernel_launch(void* const* d_in, const int* in_sizes, int n_in,
                              void* d_out, int out_size) {
    const float* x    = (const float*)d_in[0];
    const int*   ei   = (const int*)d_in[1];
    const float* g1w  = (const float*)d_in[2];
    const float* g1b  = (const float*)d_in[3];
    const float* fc2w = (const float*)d_in[4];
    const float* g3w  = (const float*)d_in[5];
    const float* g3b  = (const float*)d_in[6];
    const float* fc4w = (const float*)d_in[7];
    const float* g5w  = (const float*)d_in[8];
    const float* g5b  = (const float*)d_in[9];
    const float* fc6w = (const float*)d_in[10];

    int n = in_sizes[0] / 128;
    int E = in_sizes[1] / 2;
    const int* src = ei;
    const int* dst = ei + E;

    float *dinv, *bA, *bB, *bC;
    cudaGetSymbolAddress((void**)&dinv, g_dinv);
    cudaGetSymbolAddress((void**)&bA, g_bufA);
    cudaGetSymbolAddress((void**)&bB, g_bufB);
    cudaGetSymbolAddress((void**)&bC, g_bufC);

    // dinv = rsqrt(1 + in-degree)
    deg_init_kernel<<<(n + 255) / 256, 256>>>(dinv, n);
    deg_count_kernel<<<(E + 255) / 256, 256>>>(dst, dinv, E);
    deg_fin_kernel<<<(n + 255) / 256, 256>>>(dinv, n);

    // ---- layer 1 ----
    // bA = h1 = x @ W1 ; bB = g1b + h1*dinv^2 (self-loop + bias init)
    launch_wmma<128, 128, true, false, 1>(x, g1w, bA, bB, g1b, dinv, n);
    edge_agg128_kernel<<<(E * 32 + 255) / 256, 256>>>(src, dst, dinv, bA, bB, E);
    // bA = z1' = relu(relu(bB) + relu(bB) @ fc2w^T)
    launch_wmma<128, 128, false, true, 0>(bB, fc2w, bA, nullptr, nullptr, nullptr, n);

    // ---- layer 2 ----
    // bB = h2 = z1' @ W3 ; bC = g3b + h2*dinv^2
    launch_wmma<128, 64, true, false, 1>(bA, g3w, bB, bC, g3b, dinv, n);
    edge_agg64_kernel<<<(E * 16 + 255) / 256, 256>>>(src, dst, dinv, bB, bC, E);
    // bA = z2' = relu(relu(bC) + relu(bC) @ fc4w^T) ; bB = z2'*dinv^2
    launch_wmma<64, 64, false, true, 2>(bC, fc4w, bA, bB, nullptr, dinv, n);

    // ---- layer 3 (aggregate first at d=64, then 64->128 GEMM) ----
    edge_agg64_kernel<<<(E * 16 + 255) / 256, 256>>>(src, dst, dinv, bA, bB, E);
    // bC = Agg(z2') @ W5 + g5b
    launch_wmma<64, 128, true, false, 3>(bB, g5w, bC, nullptr, g5b, nullptr, n);
    // out = relu(relu(bC) + relu(bC) @ fc6w^T)
    launch_wmma<128, 128, false, true, 0>(bC, fc6w, (float*)d_out, nullptr, nullptr, nullptr, n);
}

// round 4
// speedup vs baseline: 1.9668x; 1.3478x over previous
#include <cuda_runtime.h>
#include <cuda_bf16.h>
#include <math.h>
#include <stdint.h>

// ---------------------------------------------------------------------------
// GCN encoder on GB300: raw mma.sync bf16x3 GEMMs (pre-packed B fragments)
// ---------------------------------------------------------------------------

#define NMAX 100000

__device__ float g_dinv[NMAX];
__device__ float g_bufA[(size_t)NMAX * 128];
__device__ float g_bufB[(size_t)NMAX * 128];
__device__ float g_bufC[(size_t)NMAX * 128];
// Pre-packed weight fragments: 6 slots x 16384 words (hi at 0, lo at K*N/2)
__device__ uint32_t g_wfrag[6 * 16384];

// ---------------------------- degree / norm --------------------------------

__global__ void deg_init_kernel(float* __restrict__ dinv, int n) {
    int i = blockIdx.x * 256 + threadIdx.x;
    if (i < n) dinv[i] = 1.0f;
}

__global__ void deg_count_kernel(const int* __restrict__ dst, float* __restrict__ dinv, int E) {
    int e = blockIdx.x * 256 + threadIdx.x;
    if (e < E) atomicAdd(&dinv[dst[e]], 1.0f);
}

__global__ void deg_fin_kernel(float* __restrict__ dinv, int n) {
    int i = blockIdx.x * 256 + threadIdx.x;
    if (i < n) dinv[i] = rsqrtf(dinv[i]);
}

// ---------------------------- edge aggregation -----------------------------

__device__ __forceinline__ void red_add_v4(float* p, float4 m) {
    asm volatile("red.global.v4.f32.add [%0], {%1,%2,%3,%4};"
                 :: "l"(p), "f"(m.x), "f"(m.y), "f"(m.z), "f"(m.w)
                 : "memory");
}

__global__ void edge_agg128_kernel(const int* __restrict__ src,
                                   const int* __restrict__ dst,
                                   const float* __restrict__ dinv,
                                   const float* __restrict__ h,
                                   float* __restrict__ out, int E) {
    int t = blockIdx.x * 256 + threadIdx.x;
    int e = t >> 5;
    int lane = t & 31;
    if (e >= E) return;
    int s = __ldg(&src[e]);
    int d = __ldg(&dst[e]);
    float norm = __ldg(&dinv[s]) * __ldg(&dinv[d]);
    float4 v = *(const float4*)(h + (size_t)s * 128 + lane * 4);
    float4 m;
    m.x = v.x * norm; m.y = v.y * norm; m.z = v.z * norm; m.w = v.w * norm;
    red_add_v4(out + (size_t)d * 128 + lane * 4, m);
}

__global__ void edge_agg64_kernel(const int* __restrict__ src,
                                  const int* __restrict__ dst,
                                  const float* __restrict__ dinv,
                                  const float* __restrict__ h,
                                  float* __restrict__ out, int E) {
    int t = blockIdx.x * 256 + threadIdx.x;
    int e = t >> 4;
    int lane = t & 15;
    if (e >= E) return;
    int s = __ldg(&src[e]);
    int d = __ldg(&dst[e]);
    float norm = __ldg(&dinv[s]) * __ldg(&dinv[d]);
    float4 v = *(const float4*)(h + (size_t)s * 64 + lane * 4);
    float4 m;
    m.x = v.x * norm; m.y = v.y * norm; m.z = v.z * norm; m.w = v.w * norm;
    red_add_v4(out + (size_t)d * 64 + lane * 4, m);
}

// ------------------------- weight fragment packing --------------------------
// Packs logical B[k][n] (k in [0,K), n in [0,N)) into m16n8k16 .row.col B
// fragments, hi/lo bf16 split. TRANS: B[k][n] = W[k*N+n] (GCN weight [K,N]);
// else B[k][n] = W[n*K+k] (nn.Linear weight [N,K]).
// Layout: word[( (kt*NT + nt)*32 + lane )*2 + r], hi at 0, lo at +K*N/2.

template <int K, int N, bool TRANS>
__global__ void wprep_kernel(const float* __restrict__ W, uint32_t* __restrict__ out) {
    constexpr int NT = N / 8;
    constexpr int KT = K / 16;
    constexpr int TOT = KT * NT * 32;
    constexpr int LOFF = K * N / 2;
    int idx = blockIdx.x * 256 + threadIdx.x;
    if (idx >= TOT) return;
    int lane = idx & 31;
    int tile = idx >> 5;
    int nt = tile % NT;
    int kt = tile / NT;
    int g = lane >> 2, tig = lane & 3;
    int nn = nt * 8 + g;
#pragma unroll
    for (int r = 0; r < 2; r++) {
        int k0 = kt * 16 + tig * 2 + r * 8;
        float v0 = TRANS ? W[(size_t)k0 * N + nn] : W[(size_t)nn * K + k0];
        float v1 = TRANS ? W[(size_t)(k0 + 1) * N + nn] : W[(size_t)nn * K + k0 + 1];
        __nv_bfloat16 h0 = __float2bfloat16(v0), h1 = __float2bfloat16(v1);
        float l0 = v0 - __bfloat162float(h0), l1 = v1 - __bfloat162float(h1);
        __nv_bfloat162 hp; hp.x = h0; hp.y = h1;
        __nv_bfloat162 lp; lp.x = __float2bfloat16(l0); lp.y = __float2bfloat16(l1);
        out[(size_t)(tile * 32 + lane) * 2 + r] = *(uint32_t*)&hp;
        out[LOFF + (size_t)(tile * 32 + lane) * 2 + r] = *(uint32_t*)&lp;
    }
}

// --------------------------------- MMA GEMM --------------------------------
// C[n, N] = act(A[n, K]) @ B  via bf16 split-3 (hi*hi + hi*lo + lo*hi).
// EPI: 0 = relu(actA + d) -> C                          (needs K == N)
//      1 = d -> C ; bias + d*dinv^2 -> C2
//      2 = relu(actA + d) -> C ; same * dinv^2 -> C2    (needs K == N)
//      3 = d + bias -> C
// Tile: 128 rows x N cols per CTA, 8 warps. A hi/lo in SMEM only.

__device__ __forceinline__ void mma_bf16(float* c, const uint32_t* a, uint32_t b0, uint32_t b1) {
    asm volatile(
        "mma.sync.aligned.m16n8k16.row.col.f32.bf16.bf16.f32 "
        "{%0,%1,%2,%3}, {%4,%5,%6,%7}, {%8,%9}, {%0,%1,%2,%3};"
        : "+f"(c[0]), "+f"(c[1]), "+f"(c[2]), "+f"(c[3])
        : "r"(a[0]), "r"(a[1]), "r"(a[2]), "r"(a[3]), "r"(b0), "r"(b1));
}

template <int K, int N, bool RELU_IN, int EPI>
__global__ __launch_bounds__(256, 2) void mma_gemm_kernel(
    const float* __restrict__ A, const uint32_t* __restrict__ WF,
    float* __restrict__ C, float* __restrict__ C2,
    const float* __restrict__ bias, const float* __restrict__ dinv, int n) {
    constexpr int LDA = K + 8;         // bf16 elems
    constexpr int NT = N / 8;          // total n8 tiles
    constexpr int KT = K / 16;
    constexpr int WN = N / 64;         // warps along N (2 or 1)
    constexpr int WM = 8 / WN;         // warps along M
    constexpr int MT = 128 / (WM * 16);// m16 tiles per warp
    constexpr int LOFF = K * N / 2;

    extern __shared__ __align__(16) char smem[];
    __nv_bfloat16* Ah = (__nv_bfloat16*)smem;
    __nv_bfloat16* Al = Ah + 128 * LDA;

    const int tid = threadIdx.x;
    const int w = tid >> 5;
    const int lane = tid & 31;
    const int g = lane >> 2, tig = lane & 3;
    const int row0 = blockIdx.x * 128;
    const int wm = w / WN;
    const int wn = w % WN;

    // ---- stage A (optional relu, hi/lo split) ----
    constexpr int KQ = K / 4;
    for (int idx = tid; idx < 128 * KQ; idx += 256) {
        int r = idx / KQ;
        int k0 = (idx - r * KQ) * 4;
        float4 v = make_float4(0.f, 0.f, 0.f, 0.f);
        if (row0 + r < n) v = *(const float4*)(A + (size_t)(row0 + r) * K + k0);
        if (RELU_IN) {
            v.x = fmaxf(v.x, 0.f); v.y = fmaxf(v.y, 0.f);
            v.z = fmaxf(v.z, 0.f); v.w = fmaxf(v.w, 0.f);
        }
        __nv_bfloat16 h0 = __float2bfloat16(v.x), h1 = __float2bfloat16(v.y);
        __nv_bfloat16 h2 = __float2bfloat16(v.z), h3 = __float2bfloat16(v.w);
        __nv_bfloat162 hp0; hp0.x = h0; hp0.y = h1;
        __nv_bfloat162 hp1; hp1.x = h2; hp1.y = h3;
        __nv_bfloat162 lp0, lp1;
        lp0.x = __float2bfloat16(v.x - __bfloat162float(h0));
        lp0.y = __float2bfloat16(v.y - __bfloat162float(h1));
        lp1.x = __float2bfloat16(v.z - __bfloat162float(h2));
        lp1.y = __float2bfloat16(v.w - __bfloat162float(h3));
        *(uint2*)(Ah + r * LDA + k0) = make_uint2(*(uint32_t*)&hp0, *(uint32_t*)&hp1);
        *(uint2*)(Al + r * LDA + k0) = make_uint2(*(uint32_t*)&lp0, *(uint32_t*)&lp1);
    }
    __syncthreads();

    // ---- mainloop ----
    float acc[MT][8][4];
#pragma unroll
    for (int mt = 0; mt < MT; mt++)
#pragma unroll
        for (int nt = 0; nt < 8; nt++)
#pragma unroll
            for (int i = 0; i < 4; i++) acc[mt][nt][i] = 0.f;

#pragma unroll
    for (int kt = 0; kt < KT; kt++) {
        uint32_t ah[MT][4], al[MT][4];
#pragma unroll
        for (int mt = 0; mt < MT; mt++) {
            const __nv_bfloat16* ab = Ah + (wm * MT * 16 + mt * 16) * LDA + kt * 16;
            const __nv_bfloat16* lb = Al + (wm * MT * 16 + mt * 16) * LDA + kt * 16;
            ah[mt][0] = *(const uint32_t*)(ab + g * LDA + tig * 2);
            ah[mt][1] = *(const uint32_t*)(ab + (g + 8) * LDA + tig * 2);
            ah[mt][2] = *(const uint32_t*)(ab + g * LDA + tig * 2 + 8);
            ah[mt][3] = *(const uint32_t*)(ab + (g + 8) * LDA + tig * 2 + 8);
            al[mt][0] = *(const uint32_t*)(lb + g * LDA + tig * 2);
            al[mt][1] = *(const uint32_t*)(lb + (g + 8) * LDA + tig * 2);
            al[mt][2] = *(const uint32_t*)(lb + g * LDA + tig * 2 + 8);
            al[mt][3] = *(const uint32_t*)(lb + (g + 8) * LDA + tig * 2 + 8);
        }
#pragma unroll
        for (int nt = 0; nt < 8; nt++) {
            int gnt = wn * 8 + nt;
            const uint32_t* bp = WF + ((size_t)(kt * NT + gnt) * 32 + lane) * 2;
            uint2 bh = *(const uint2*)bp;
            uint2 bl = *(const uint2*)(bp + LOFF);
#pragma unroll
            for (int mt = 0; mt < MT; mt++) {
                mma_bf16(acc[mt][nt], ah[mt], bh.x, bh.y);
                mma_bf16(acc[mt][nt], ah[mt], bl.x, bl.y);
                mma_bf16(acc[mt][nt], al[mt], bh.x, bh.y);
            }
        }
    }

    // ---- epilogue straight from registers ----
#pragma unroll
    for (int mt = 0; mt < MT; mt++) {
        int rbase = wm * MT * 16 + mt * 16;
#pragma unroll
        for (int h = 0; h < 2; h++) {
            int rloc = rbase + g + h * 8;
            int row = row0 + rloc;
            if (row >= n) continue;
            float s = 0.f;
            if (EPI == 1 || EPI == 2) {
                float dv = __ldg(&dinv[row]);
                s = dv * dv;
            }
#pragma unroll
            for (int nt = 0; nt < 8; nt++) {
                int col = wn * 64 + nt * 8 + tig * 2;
                float d0 = acc[mt][nt][h * 2 + 0];
                float d1 = acc[mt][nt][h * 2 + 1];
                float v0, v1, u0 = 0.f, u1 = 0.f;
                if (EPI == 0 || EPI == 2) {
                    float r0 = __bfloat162float(Ah[rloc * LDA + col]) +
                               __bfloat162float(Al[rloc * LDA + col]);
                    float r1 = __bfloat162float(Ah[rloc * LDA + col + 1]) +
                               __bfloat162float(Al[rloc * LDA + col + 1]);
                    v0 = fmaxf(r0 + d0, 0.f);
                    v1 = fmaxf(r1 + d1, 0.f);
                    if (EPI == 2) { u0 = v0 * s; u1 = v1 * s; }
                } else if (EPI == 1) {
                    v0 = d0; v1 = d1;
                    u0 = __ldg(&bias[col]) + d0 * s;
                    u1 = __ldg(&bias[col + 1]) + d1 * s;
                } else {
                    v0 = d0 + __ldg(&bias[col]);
                    v1 = d1 + __ldg(&bias[col + 1]);
                }
                float2 o; o.x = v0; o.y = v1;
                *(float2*)(C + (size_t)row * N + col) = o;
                if (EPI == 1 || EPI == 2) {
                    float2 o2; o2.x = u0; o2.y = u1;
                    *(float2*)(C2 + (size_t)row * N + col) = o2;
                }
            }
        }
    }
}

template <int K, int N, bool RELU_IN, int EPI>
static void launch_mma(const float* A, const uint32_t* WF, float* C, float* C2,
                       const float* bias, const float* dinv, int n) {
    constexpr int SMEM = 2 * 128 * (K + 8) * 2;
    auto kfn = mma_gemm_kernel<K, N, RELU_IN, EPI>;
    if (SMEM > 48 * 1024)
        cudaFuncSetAttribute(kfn, cudaFuncAttributeMaxDynamicSharedMemorySize, SMEM);
    kfn<<<(n + 127) / 128, 256, SMEM>>>(A, WF, C, C2, bias, dinv, n);
}

// --------------------------------- driver ----------------------------------

extern "C" void kernel_launch(void* const* d_in, const int* in_sizes, int n_in,
                              void* d_out, int out_size) {
    const float* x    = (const float*)d_in[0];
    const int*   ei   = (const int*)d_in[1];
    const float* g1w  = (const float*)d_in[2];
    const float* g1b  = (const float*)d_in[3];
    const float* fc2w = (const float*)d_in[4];
    const float* g3w  = (const float*)d_in[5];
    const float* g3b  = (const float*)d_in[6];
    const float* fc4w = (const float*)d_in[7];
    const float* g5w  = (const float*)d_in[8];
    const float* g5b  = (const float*)d_in[9];
    const float* fc6w = (const float*)d_in[10];

    int n = in_sizes[0] / 128;
    int E = in_sizes[1] / 2;
    const int* src = ei;
    const int* dst = ei + E;

    float *dinv, *bA, *bB, *bC;
    uint32_t* wf;
    cudaGetSymbolAddress((void**)&dinv, g_dinv);
    cudaGetSymbolAddress((void**)&bA, g_bufA);
    cudaGetSymbolAddress((void**)&bB, g_bufB);
    cudaGetSymbolAddress((void**)&bC, g_bufC);
    cudaGetSymbolAddress((void**)&wf, g_wfrag);
    uint32_t* wf0 = wf;              // g1w  128x128 T
    uint32_t* wf1 = wf + 16384;      // fc2w 128x128
    uint32_t* wf2 = wf + 2 * 16384;  // g3w  128x64 T
    uint32_t* wf3 = wf + 3 * 16384;  // fc4w 64x64
    uint32_t* wf4 = wf + 4 * 16384;  // g5w  64x128 T
    uint32_t* wf5 = wf + 5 * 16384;  // fc6w 128x128

    // weight fragment packing (cheap, graph-resident)
    wprep_kernel<128, 128, true ><<<16, 256>>>(g1w, wf0);
    wprep_kernel<128, 128, false><<<16, 256>>>(fc2w, wf1);
    wprep_kernel<128, 64,  true ><<<8, 256>>>(g3w, wf2);
    wprep_kernel<64,  64,  false><<<4, 256>>>(fc4w, wf3);
    wprep_kernel<64,  128, true ><<<8, 256>>>(g5w, wf4);
    wprep_kernel<128, 128, false><<<16, 256>>>(fc6w, wf5);

    // dinv = rsqrt(1 + in-degree)
    deg_init_kernel<<<(n + 255) / 256, 256>>>(dinv, n);
    deg_count_kernel<<<(E + 255) / 256, 256>>>(dst, dinv, E);
    deg_fin_kernel<<<(n + 255) / 256, 256>>>(dinv, n);

    // ---- layer 1 ----
    // bA = h1 = x @ W1 ; bB = g1b + h1*dinv^2
    launch_mma<128, 128, false, 1>(x, wf0, bA, bB, g1b, dinv, n);
    edge_agg128_kernel<<<(E * 32 + 255) / 256, 256>>>(src, dst, dinv, bA, bB, E);
    // bA = z1' = relu(relu(bB) + relu(bB) @ fc2w^T)
    launch_mma<128, 128, true, 0>(bB, wf1, bA, nullptr, nullptr, nullptr, n);

    // ---- layer 2 ----
    // bB = h2 = z1' @ W3 ; bC = g3b + h2*dinv^2
    launch_mma<128, 64, false, 1>(bA, wf2, bB, bC, g3b, dinv, n);
    edge_agg64_kernel<<<(E * 16 + 255) / 256, 256>>>(src, dst, dinv, bB, bC, E);
    // bA = z2' = relu(relu(bC) + relu(bC) @ fc4w^T) ; bB = z2'*dinv^2
    launch_mma<64, 64, true, 2>(bC, wf3, bA, bB, nullptr, dinv, n);

    // ---- layer 3 (aggregate first at d=64, then 64->128 GEMM) ----
    edge_agg64_kernel<<<(E * 16 + 255) / 256, 256>>>(src, dst, dinv, bA, bB, E);
    // bC = Agg(z2') @ W5 + g5b
    launch_mma<64, 128, false, 3>(bB, wf4, bC, nullptr, g5b, nullptr, n);
    // out = relu(relu(bC) + relu(bC) @ fc6w^T)
    launch_mma<128, 128, true, 0>(bC, wf5, (float*)d_out, nullptr, nullptr, nullptr, n);
}

// round 5
// speedup vs baseline: 2.0192x; 1.0266x over previous
#include <cuda_runtime.h>
#include <cuda_bf16.h>
#include <math.h>
#include <stdint.h>

// ---------------------------------------------------------------------------
// GCN encoder on GB300: raw mma.sync bf16x3 GEMMs + norm-precomputed edge agg
// ---------------------------------------------------------------------------

#define NMAX 100000
#define EMAX 2000000

__device__ float g_cnt[NMAX];                    // degree counts (incl self-loop)
__device__ float g_norm[EMAX];                   // per-edge norm
__device__ float g_bufA[(size_t)NMAX * 128];
__device__ float g_bufB[(size_t)NMAX * 128];
__device__ float g_bufC[(size_t)NMAX * 128];
__device__ uint32_t g_wfrag[6 * 16384];          // pre-packed weight fragments

// ---------------------------- degree / norm --------------------------------

__global__ void deg_init_kernel(float* __restrict__ cnt, int n) {
    int i = blockIdx.x * 256 + threadIdx.x;
    if (i < n) cnt[i] = 1.0f;
}

__global__ void deg_count_kernel(const int* __restrict__ dst, float* __restrict__ cnt, int E) {
    int e = blockIdx.x * 256 + threadIdx.x;
    if (e < E) atomicAdd(&cnt[dst[e]], 1.0f);
}

__global__ void norm_kernel(const int* __restrict__ src, const int* __restrict__ dst,
                            const float* __restrict__ cnt, float* __restrict__ norm, int E) {
    int e = blockIdx.x * 256 + threadIdx.x;
    if (e < E) norm[e] = rsqrtf(__ldg(&cnt[src[e]])) * rsqrtf(__ldg(&cnt[dst[e]]));
}

// ---------------------------- edge aggregation -----------------------------

__device__ __forceinline__ void red_add_v4(float* p, float4 m) {
    asm volatile("red.global.v4.f32.add [%0], {%1,%2,%3,%4};"
                 :: "l"(p), "f"(m.x), "f"(m.y), "f"(m.z), "f"(m.w)
                 : "memory");
}

__global__ void edge_agg128_kernel(const int* __restrict__ src,
                                   const int* __restrict__ dst,
                                   const float* __restrict__ norm,
                                   const float* __restrict__ h,
                                   float* __restrict__ out, int E) {
    int t = blockIdx.x * 256 + threadIdx.x;
    int e = t >> 5;
    int lane = t & 31;
    if (e >= E) return;
    int s = __ldg(&src[e]);
    int d = __ldg(&dst[e]);
    float nrm = __ldg(&norm[e]);
    float4 v = *(const float4*)(h + (size_t)s * 128 + lane * 4);
    float4 m;
    m.x = v.x * nrm; m.y = v.y * nrm; m.z = v.z * nrm; m.w = v.w * nrm;
    red_add_v4(out + (size_t)d * 128 + lane * 4, m);
}

__global__ void edge_agg64_kernel(const int* __restrict__ src,
                                  const int* __restrict__ dst,
                                  const float* __restrict__ norm,
                                  const float* __restrict__ h,
                                  float* __restrict__ out, int E) {
    int t = blockIdx.x * 256 + threadIdx.x;
    int e = t >> 4;
    int lane = t & 15;
    if (e >= E) return;
    int s = __ldg(&src[e]);
    int d = __ldg(&dst[e]);
    float nrm = __ldg(&norm[e]);
    float4 v = *(const float4*)(h + (size_t)s * 64 + lane * 4);
    float4 m;
    m.x = v.x * nrm; m.y = v.y * nrm; m.z = v.z * nrm; m.w = v.w * nrm;
    red_add_v4(out + (size_t)d * 64 + lane * 4, m);
}

// ------------------------- weight fragment packing --------------------------
// All 6 weights in ONE kernel. Packs logical B[k][n] into m16n8k16 .row.col B
// fragments, hi/lo bf16 split. Slot stride 16384 words; lo at +K*N/2.
// Tile ranges (KT*NT): g1w 128 | fc2w 128 | g3w 64 | fc4w 32 | g5w 64 | fc6w 128

__global__ void wprep_all_kernel(const float* __restrict__ w0, const float* __restrict__ w1,
                                 const float* __restrict__ w2, const float* __restrict__ w3,
                                 const float* __restrict__ w4, const float* __restrict__ w5,
                                 uint32_t* __restrict__ wf) {
    int idx = blockIdx.x * 256 + threadIdx.x;
    int tile = idx >> 5;
    if (tile >= 544) return;
    int lane = idx & 31;

    const float* W;
    int K, N, slot, base;
    bool TR;
    if (tile < 128)      { slot = 0; base = 0;   W = w0; K = 128; N = 128; TR = true;  }
    else if (tile < 256) { slot = 1; base = 128; W = w1; K = 128; N = 128; TR = false; }
    else if (tile < 320) { slot = 2; base = 256; W = w2; K = 128; N = 64;  TR = true;  }
    else if (tile < 352) { slot = 3; base = 320; W = w3; K = 64;  N = 64;  TR = false; }
    else if (tile < 416) { slot = 4; base = 352; W = w4; K = 64;  N = 128; TR = true;  }
    else                 { slot = 5; base = 416; W = w5; K = 128; N = 128; TR = false; }

    int t = tile - base;
    int NT = N / 8;
    int nt = t % NT;
    int kt = t / NT;
    int g = lane >> 2, tig = lane & 3;
    int nn = nt * 8 + g;
    uint32_t* out = wf + slot * 16384;
    int LOFF = K * N / 2;

#pragma unroll
    for (int r = 0; r < 2; r++) {
        int k0 = kt * 16 + tig * 2 + r * 8;
        float v0 = TR ? W[(size_t)k0 * N + nn] : W[(size_t)nn * K + k0];
        float v1 = TR ? W[(size_t)(k0 + 1) * N + nn] : W[(size_t)nn * K + k0 + 1];
        __nv_bfloat16 h0 = __float2bfloat16(v0), h1 = __float2bfloat16(v1);
        float l0 = v0 - __bfloat162float(h0), l1 = v1 - __bfloat162float(h1);
        __nv_bfloat162 hp; hp.x = h0; hp.y = h1;
        __nv_bfloat162 lp; lp.x = __float2bfloat16(l0); lp.y = __float2bfloat16(l1);
        out[(size_t)(t * 32 + lane) * 2 + r] = *(uint32_t*)&hp;
        out[LOFF + (size_t)(t * 32 + lane) * 2 + r] = *(uint32_t*)&lp;
    }
}

// --------------------------------- MMA GEMM --------------------------------
// C[n, N] = act(A[n, K]) @ B  via bf16 split-3 (hi*hi + hi*lo + lo*hi).
// EPI: 0 = relu(actA + d) -> C                          (needs K == N)
//      1 = d -> C ; bias + d/cnt -> C2
//      2 = relu(actA + d) -> C ; same / cnt -> C2       (needs K == N)
//      3 = d + bias -> C
// Tile: 128 rows x N cols per CTA, 8 warps. A hi/lo in SMEM, ldmatrix loads.

__device__ __forceinline__ void mma_bf16(float* c, const uint32_t* a, uint32_t b0, uint32_t b1) {
    asm volatile(
        "mma.sync.aligned.m16n8k16.row.col.f32.bf16.bf16.f32 "
        "{%0,%1,%2,%3}, {%4,%5,%6,%7}, {%8,%9}, {%0,%1,%2,%3};"
        : "+f"(c[0]), "+f"(c[1]), "+f"(c[2]), "+f"(c[3])
        : "r"(a[0]), "r"(a[1]), "r"(a[2]), "r"(a[3]), "r"(b0), "r"(b1));
}

__device__ __forceinline__ void ldsm_x4(uint32_t* r, uint32_t addr) {
    asm volatile("ldmatrix.sync.aligned.m8n8.x4.shared.b16 {%0,%1,%2,%3}, [%4];"
                 : "=r"(r[0]), "=r"(r[1]), "=r"(r[2]), "=r"(r[3]) : "r"(addr));
}

__device__ __forceinline__ uint32_t smem_u32(const void* p) {
    uint32_t a;
    asm("{ .reg .u64 t; cvta.to.shared.u64 t, %1; cvt.u32.u64 %0, t; }" : "=r"(a) : "l"(p));
    return a;
}

template <int K, int N, bool RELU_IN, int EPI>
__global__ __launch_bounds__(256, 2) void mma_gemm_kernel(
    const float* __restrict__ A, const uint32_t* __restrict__ WF,
    float* __restrict__ C, float* __restrict__ C2,
    const float* __restrict__ bias, const float* __restrict__ cnt, int n) {
    constexpr int LDA = K + 8;          // bf16 elems
    constexpr int NT = N / 8;
    constexpr int KT = K / 16;
    constexpr int WN = N / 64;          // warps along N (2 or 1)
    constexpr int WM = 8 / WN;          // warps along M
    constexpr int MT = 128 / (WM * 16); // m16 tiles per warp
    constexpr int LOFF = K * N / 2;

    extern __shared__ __align__(16) char smem[];
    __nv_bfloat16* Ah = (__nv_bfloat16*)smem;
    __nv_bfloat16* Al = Ah + 128 * LDA;

    const int tid = threadIdx.x;
    const int w = tid >> 5;
    const int lane = tid & 31;
    const int g = lane >> 2, tig = lane & 3;
    const int row0 = blockIdx.x * 128;
    const int wm = w / WN;
    const int wn = w % WN;

    // ---- stage A (optional relu, hi/lo split) ----
    constexpr int KQ = K / 4;
    for (int idx = tid; idx < 128 * KQ; idx += 256) {
        int r = idx / KQ;
        int k0 = (idx - r * KQ) * 4;
        float4 v = make_float4(0.f, 0.f, 0.f, 0.f);
        if (row0 + r < n) v = *(const float4*)(A + (size_t)(row0 + r) * K + k0);
        if (RELU_IN) {
            v.x = fmaxf(v.x, 0.f); v.y = fmaxf(v.y, 0.f);
            v.z = fmaxf(v.z, 0.f); v.w = fmaxf(v.w, 0.f);
        }
        __nv_bfloat16 h0 = __float2bfloat16(v.x), h1 = __float2bfloat16(v.y);
        __nv_bfloat16 h2 = __float2bfloat16(v.z), h3 = __float2bfloat16(v.w);
        __nv_bfloat162 hp0; hp0.x = h0; hp0.y = h1;
        __nv_bfloat162 hp1; hp1.x = h2; hp1.y = h3;
        __nv_bfloat162 lp0, lp1;
        lp0.x = __float2bfloat16(v.x - __bfloat162float(h0));
        lp0.y = __float2bfloat16(v.y - __bfloat162float(h1));
        lp1.x = __float2bfloat16(v.z - __bfloat162float(h2));
        lp1.y = __float2bfloat16(v.w - __bfloat162float(h3));
        *(uint2*)(Ah + r * LDA + k0) = make_uint2(*(uint32_t*)&hp0, *(uint32_t*)&hp1);
        *(uint2*)(Al + r * LDA + k0) = make_uint2(*(uint32_t*)&lp0, *(uint32_t*)&lp1);
    }
    __syncthreads();

    // ---- mainloop ----
    float acc[MT][8][4];
#pragma unroll
    for (int mt = 0; mt < MT; mt++)
#pragma unroll
        for (int nt = 0; nt < 8; nt++)
#pragma unroll
            for (int i = 0; i < 4; i++) acc[mt][nt][i] = 0.f;

    // ldmatrix base: lane -> (row = lane&15, col8 = (lane>>4)*8) of warp's A tile
    const uint32_t a_base =
        smem_u32(Ah) + (uint32_t)(((wm * MT * 16 + (lane & 15)) * LDA + (lane >> 4) * 8) * 2);
    const uint32_t l_base = a_base + (uint32_t)(128 * LDA * 2);

#pragma unroll
    for (int kt = 0; kt < KT; kt++) {
        uint32_t ah[MT][4], al[MT][4];
#pragma unroll
        for (int mt = 0; mt < MT; mt++) {
            uint32_t off = (uint32_t)((mt * 16 * LDA + kt * 16) * 2);
            ldsm_x4(ah[mt], a_base + off);
            ldsm_x4(al[mt], l_base + off);
        }
#pragma unroll
        for (int nt = 0; nt < 8; nt++) {
            int gnt = wn * 8 + nt;
            const uint32_t* bp = WF + ((size_t)(kt * NT + gnt) * 32 + lane) * 2;
            uint2 bh = *(const uint2*)bp;
            uint2 bl = *(const uint2*)(bp + LOFF);
#pragma unroll
            for (int mt = 0; mt < MT; mt++) {
                mma_bf16(acc[mt][nt], ah[mt], bh.x, bh.y);
                mma_bf16(acc[mt][nt], ah[mt], bl.x, bl.y);
                mma_bf16(acc[mt][nt], al[mt], bh.x, bh.y);
            }
        }
    }

    // ---- epilogue straight from registers ----
#pragma unroll
    for (int mt = 0; mt < MT; mt++) {
        int rbase = wm * MT * 16 + mt * 16;
#pragma unroll
        for (int h = 0; h < 2; h++) {
            int rloc = rbase + g + h * 8;
            int row = row0 + rloc;
            if (row >= n) continue;
            float s = 0.f;
            if (EPI == 1 || EPI == 2) s = 1.0f / __ldg(&cnt[row]);
#pragma unroll
            for (int nt = 0; nt < 8; nt++) {
                int col = wn * 64 + nt * 8 + tig * 2;
                float d0 = acc[mt][nt][h * 2 + 0];
                float d1 = acc[mt][nt][h * 2 + 1];
                float v0, v1, u0 = 0.f, u1 = 0.f;
                if (EPI == 0 || EPI == 2) {
                    __nv_bfloat162 rh = *(const __nv_bfloat162*)(Ah + rloc * LDA + col);
                    __nv_bfloat162 rl = *(const __nv_bfloat162*)(Al + rloc * LDA + col);
                    float r0 = __bfloat162float(rh.x) + __bfloat162float(rl.x);
                    float r1 = __bfloat162float(rh.y) + __bfloat162float(rl.y);
                    v0 = fmaxf(r0 + d0, 0.f);
                    v1 = fmaxf(r1 + d1, 0.f);
                    if (EPI == 2) { u0 = v0 * s; u1 = v1 * s; }
                } else if (EPI == 1) {
                    v0 = d0; v1 = d1;
                    u0 = __ldg(&bias[col]) + d0 * s;
                    u1 = __ldg(&bias[col + 1]) + d1 * s;
                } else {
                    v0 = d0 + __ldg(&bias[col]);
                    v1 = d1 + __ldg(&bias[col + 1]);
                }
                float2 o; o.x = v0; o.y = v1;
                *(float2*)(C + (size_t)row * N + col) = o;
                if (EPI == 1 || EPI == 2) {
                    float2 o2; o2.x = u0; o2.y = u1;
                    *(float2*)(C2 + (size_t)row * N + col) = o2;
                }
            }
        }
    }
}

template <int K, int N, bool RELU_IN, int EPI>
static void launch_mma(const float* A, const uint32_t* WF, float* C, float* C2,
                       const float* bias, const float* cnt, int n) {
    constexpr int SMEM = 2 * 128 * (K + 8) * 2;
    auto kfn = mma_gemm_kernel<K, N, RELU_IN, EPI>;
    if (SMEM > 48 * 1024)
        cudaFuncSetAttribute(kfn, cudaFuncAttributeMaxDynamicSharedMemorySize, SMEM);
    kfn<<<(n + 127) / 128, 256, SMEM>>>(A, WF, C, C2, bias, cnt, n);
}

// --------------------------------- driver ----------------------------------

extern "C" void kernel_launch(void* const* d_in, const int* in_sizes, int n_in,
                              void* d_out, int out_size) {
    const float* x    = (const float*)d_in[0];
    const int*   ei   = (const int*)d_in[1];
    const float* g1w  = (const float*)d_in[2];
    const float* g1b  = (const float*)d_in[3];
    const float* fc2w = (const float*)d_in[4];
    const float* g3w  = (const float*)d_in[5];
    const float* g3b  = (const float*)d_in[6];
    const float* fc4w = (const float*)d_in[7];
    const float* g5w  = (const float*)d_in[8];
    const float* g5b  = (const float*)d_in[9];
    const float* fc6w = (const float*)d_in[10];

    int n = in_sizes[0] / 128;
    int E = in_sizes[1] / 2;
    const int* src = ei;
    const int* dst = ei + E;

    float *cnt, *nrm, *bA, *bB, *bC;
    uint32_t* wf;
    cudaGetSymbolAddress((void**)&cnt, g_cnt);
    cudaGetSymbolAddress((void**)&nrm, g_norm);
    cudaGetSymbolAddress((void**)&bA, g_bufA);
    cudaGetSymbolAddress((void**)&bB, g_bufB);
    cudaGetSymbolAddress((void**)&bC, g_bufC);
    cudaGetSymbolAddress((void**)&wf, g_wfrag);
    uint32_t* wf0 = wf;              // g1w  128x128 T
    uint32_t* wf1 = wf + 16384;      // fc2w 128x128
    uint32_t* wf2 = wf + 2 * 16384;  // g3w  128x64 T
    uint32_t* wf3 = wf + 3 * 16384;  // fc4w 64x64
    uint32_t* wf4 = wf + 4 * 16384;  // g5w  64x128 T
    uint32_t* wf5 = wf + 5 * 16384;  // fc6w 128x128

    // prep: weights (one kernel) + degree/norm
    wprep_all_kernel<<<68, 256>>>(g1w, fc2w, g3w, fc4w, g5w, fc6w, wf);
    deg_init_kernel<<<(n + 255) / 256, 256>>>(cnt, n);
    deg_count_kernel<<<(E + 255) / 256, 256>>>(dst, cnt, E);
    norm_kernel<<<(E + 255) / 256, 256>>>(src, dst, cnt, nrm, E);

    // ---- layer 1 ----
    // bA = h1 = x @ W1 ; bB = g1b + h1/cnt (self-loop + bias init)
    launch_mma<128, 128, false, 1>(x, wf0, bA, bB, g1b, cnt, n);
    edge_agg128_kernel<<<(E * 32 + 255) / 256, 256>>>(src, dst, nrm, bA, bB, E);
    // bA = z1' = relu(relu(bB) + relu(bB) @ fc2w^T)
    launch_mma<128, 128, true, 0>(bB, wf1, bA, nullptr, nullptr, nullptr, n);

    // ---- layer 2 ----
    // bB = h2 = z1' @ W3 ; bC = g3b + h2/cnt
    launch_mma<128, 64, false, 1>(bA, wf2, bB, bC, g3b, cnt, n);
    edge_agg64_kernel<<<(E * 16 + 255) / 256, 256>>>(src, dst, nrm, bB, bC, E);
    // bA = z2' = relu(relu(bC) + relu(bC) @ fc4w^T) ; bB = z2'/cnt
    launch_mma<64, 64, true, 2>(bC, wf3, bA, bB, nullptr, cnt, n);

    // ---- layer 3 (aggregate first at d=64, then 64->128 GEMM) ----
    edge_agg64_kernel<<<(E * 16 + 255) / 256, 256>>>(src, dst, nrm, bA, bB, E);
    // bC = Agg(z2') @ W5 + g5b
    launch_mma<64, 128, false, 3>(bB, wf4, bC, nullptr, g5b, nullptr, n);
    // out = relu(relu(bC) + relu(bC) @ fc6w^T)
    launch_mma<128, 128, true, 0>(bC, wf5, (float*)d_out, nullptr, nullptr, nullptr, n);
}

// round 6
// speedup vs baseline: 3.1307x; 1.5504x over previous
#include <cuda_runtime.h>
#include <cuda_bf16.h>
#include <math.h>
#include <stdint.h>

// ---------------------------------------------------------------------------
// GCN encoder on GB300: mma.sync bf16x3 GEMMs + CSR gather aggregation
// ---------------------------------------------------------------------------

#define NMAX 100000
#define EMAX 2000000

__device__ int   g_deg[NMAX];
__device__ int   g_rs[NMAX];          // row start (exclusive scan of deg)
__device__ int   g_cursor[NMAX];
__device__ int   g_blk[512];
__device__ int   g_csrc[EMAX];        // CSR: src node per slot
__device__ float g_cnrm[EMAX];        // CSR: edge norm per slot
__device__ float g_bufA[(size_t)NMAX * 128];
__device__ float g_bufB[(size_t)NMAX * 128];
__device__ float g_bufC[(size_t)NMAX * 128];
__device__ uint32_t g_wfrag[6 * 16384];

// ------------------------------ CSR build ----------------------------------

__global__ void deg_zero_kernel(int* __restrict__ deg, int n) {
    int i = blockIdx.x * 256 + threadIdx.x;
    if (i < n) deg[i] = 0;
}

__global__ void deg_count_kernel(const int* __restrict__ dst, int* __restrict__ deg, int E) {
    int e = blockIdx.x * 256 + threadIdx.x;
    if (e < E) atomicAdd(&deg[dst[e]], 1);
}

// per-block inclusive scan (Hillis-Steele over 256)
__global__ void scan1_kernel(const int* __restrict__ deg, int* __restrict__ tmp,
                             int* __restrict__ blk, int n) {
    __shared__ int sh[256];
    int tid = threadIdx.x;
    int i = blockIdx.x * 256 + tid;
    int v = (i < n) ? deg[i] : 0;
    sh[tid] = v;
    __syncthreads();
#pragma unroll
    for (int off = 1; off < 256; off <<= 1) {
        int t = (tid >= off) ? sh[tid - off] : 0;
        __syncthreads();
        sh[tid] += t;
        __syncthreads();
    }
    if (i < n) tmp[i] = sh[tid];
    if (tid == 255) blk[blockIdx.x] = sh[255];
}

__global__ void scan2_kernel(int* __restrict__ blk, int nb) {
    if (threadIdx.x == 0 && blockIdx.x == 0) {
        int run = 0;
        for (int b = 0; b < nb; b++) {
            int t = blk[b];
            blk[b] = run;
            run += t;
        }
    }
}

__global__ void scan3_kernel(const int* __restrict__ tmp, const int* __restrict__ deg,
                             const int* __restrict__ blk, int* __restrict__ rs,
                             int* __restrict__ cursor, int n) {
    int i = blockIdx.x * 256 + threadIdx.x;
    if (i < n) {
        int v = tmp[i] - deg[i] + blk[blockIdx.x];
        rs[i] = v;
        cursor[i] = v;
    }
}

__global__ void scatter_kernel(const int* __restrict__ src, const int* __restrict__ dst,
                               const int* __restrict__ deg, int* __restrict__ cursor,
                               int* __restrict__ csrc, float* __restrict__ cnrm, int E) {
    int e = blockIdx.x * 256 + threadIdx.x;
    if (e >= E) return;
    int s = __ldg(&src[e]);
    int d = __ldg(&dst[e]);
    int pos = atomicAdd(&cursor[d], 1);
    csrc[pos] = s;
    cnrm[pos] = rsqrtf((float)(__ldg(&deg[s]) + 1)) * rsqrtf((float)(d == s ? (__ldg(&deg[d]) + 1)
                                                                             : (__ldg(&deg[d]) + 1)));
}

// ---------------------- CSR gather aggregation -----------------------------
// out[d] = (BIAS? b : 0) + h[d]/(deg[d]+1) + sum_{e in adj(d)} h[src_e]*nrm_e

template <bool BIAS>
__global__ void csr_agg128_kernel(const int* __restrict__ rs, const int* __restrict__ deg,
                                  const int* __restrict__ csrc, const float* __restrict__ cnrm,
                                  const float* __restrict__ bias,
                                  const float* __restrict__ h, float* __restrict__ out, int n) {
    int t = blockIdx.x * 256 + threadIdx.x;
    int d = t >> 5;
    int lane = t & 31;
    if (d >= n) return;
    int start = __ldg(&rs[d]);
    int dg = __ldg(&deg[d]);
    float inv = 1.0f / (float)(dg + 1);
    float4 acc = *(const float4*)(h + (size_t)d * 128 + lane * 4);
    acc.x *= inv; acc.y *= inv; acc.z *= inv; acc.w *= inv;
    if (BIAS) {
        float4 b = *(const float4*)(bias + lane * 4);
        acc.x += b.x; acc.y += b.y; acc.z += b.z; acc.w += b.w;
    }
    int j = start, end = start + dg;
    for (; j + 2 <= end; j += 2) {
        int s0 = __ldg(&csrc[j]), s1 = __ldg(&csrc[j + 1]);
        float n0 = __ldg(&cnrm[j]), n1 = __ldg(&cnrm[j + 1]);
        float4 v0 = *(const float4*)(h + (size_t)s0 * 128 + lane * 4);
        float4 v1 = *(const float4*)(h + (size_t)s1 * 128 + lane * 4);
        acc.x += v0.x * n0 + v1.x * n1;
        acc.y += v0.y * n0 + v1.y * n1;
        acc.z += v0.z * n0 + v1.z * n1;
        acc.w += v0.w * n0 + v1.w * n1;
    }
    if (j < end) {
        int s0 = __ldg(&csrc[j]);
        float n0 = __ldg(&cnrm[j]);
        float4 v0 = *(const float4*)(h + (size_t)s0 * 128 + lane * 4);
        acc.x += v0.x * n0; acc.y += v0.y * n0;
        acc.z += v0.z * n0; acc.w += v0.w * n0;
    }
    *(float4*)(out + (size_t)d * 128 + lane * 4) = acc;
}

template <bool BIAS>
__global__ void csr_agg64_kernel(const int* __restrict__ rs, const int* __restrict__ deg,
                                 const int* __restrict__ csrc, const float* __restrict__ cnrm,
                                 const float* __restrict__ bias,
                                 const float* __restrict__ h, float* __restrict__ out, int n) {
    int t = blockIdx.x * 256 + threadIdx.x;
    int d = t >> 4;
    int lane = t & 15;
    if (d >= n) return;
    int start = __ldg(&rs[d]);
    int dg = __ldg(&deg[d]);
    float inv = 1.0f / (float)(dg + 1);
    float4 acc = *(const float4*)(h + (size_t)d * 64 + lane * 4);
    acc.x *= inv; acc.y *= inv; acc.z *= inv; acc.w *= inv;
    if (BIAS) {
        float4 b = *(const float4*)(bias + lane * 4);
        acc.x += b.x; acc.y += b.y; acc.z += b.z; acc.w += b.w;
    }
    int j = start, end = start + dg;
    for (; j + 2 <= end; j += 2) {
        int s0 = __ldg(&csrc[j]), s1 = __ldg(&csrc[j + 1]);
        float n0 = __ldg(&cnrm[j]), n1 = __ldg(&cnrm[j + 1]);
        float4 v0 = *(const float4*)(h + (size_t)s0 * 64 + lane * 4);
        float4 v1 = *(const float4*)(h + (size_t)s1 * 64 + lane * 4);
        acc.x += v0.x * n0 + v1.x * n1;
        acc.y += v0.y * n0 + v1.y * n1;
        acc.z += v0.z * n0 + v1.z * n1;
        acc.w += v0.w * n0 + v1.w * n1;
    }
    if (j < end) {
        int s0 = __ldg(&csrc[j]);
        float n0 = __ldg(&cnrm[j]);
        float4 v0 = *(const float4*)(h + (size_t)s0 * 64 + lane * 4);
        acc.x += v0.x * n0; acc.y += v0.y * n0;
        acc.z += v0.z * n0; acc.w += v0.w * n0;
    }
    *(float4*)(out + (size_t)d * 64 + lane * 4) = acc;
}

// ------------------------- weight fragment packing --------------------------

__global__ void wprep_all_kernel(const float* __restrict__ w0, const float* __restrict__ w1,
                                 const float* __restrict__ w2, const float* __restrict__ w3,
                                 const float* __restrict__ w4, const float* __restrict__ w5,
                                 uint32_t* __restrict__ wf) {
    int idx = blockIdx.x * 256 + threadIdx.x;
    int tile = idx >> 5;
    if (tile >= 544) return;
    int lane = idx & 31;

    const float* W;
    int K, N, slot, base;
    bool TR;
    if (tile < 128)      { slot = 0; base = 0;   W = w0; K = 128; N = 128; TR = true;  }
    else if (tile < 256) { slot = 1; base = 128; W = w1; K = 128; N = 128; TR = false; }
    else if (tile < 320) { slot = 2; base = 256; W = w2; K = 128; N = 64;  TR = true;  }
    else if (tile < 352) { slot = 3; base = 320; W = w3; K = 64;  N = 64;  TR = false; }
    else if (tile < 416) { slot = 4; base = 352; W = w4; K = 64;  N = 128; TR = true;  }
    else                 { slot = 5; base = 416; W = w5; K = 128; N = 128; TR = false; }

    int t = tile - base;
    int NT = N / 8;
    int nt = t % NT;
    int kt = t / NT;
    int g = lane >> 2, tig = lane & 3;
    int nn = nt * 8 + g;
    uint32_t* out = wf + slot * 16384;
    int LOFF = K * N / 2;

#pragma unroll
    for (int r = 0; r < 2; r++) {
        int k0 = kt * 16 + tig * 2 + r * 8;
        float v0 = TR ? W[(size_t)k0 * N + nn] : W[(size_t)nn * K + k0];
        float v1 = TR ? W[(size_t)(k0 + 1) * N + nn] : W[(size_t)nn * K + k0 + 1];
        __nv_bfloat16 h0 = __float2bfloat16(v0), h1 = __float2bfloat16(v1);
        float l0 = v0 - __bfloat162float(h0), l1 = v1 - __bfloat162float(h1);
        __nv_bfloat162 hp; hp.x = h0; hp.y = h1;
        __nv_bfloat162 lp; lp.x = __float2bfloat16(l0); lp.y = __float2bfloat16(l1);
        out[(size_t)(t * 32 + lane) * 2 + r] = *(uint32_t*)&hp;
        out[LOFF + (size_t)(t * 32 + lane) * 2 + r] = *(uint32_t*)&lp;
    }
}

// --------------------------------- MMA GEMM --------------------------------
// C[n, N] = act(A[n, K]) @ B via bf16 split-3.
// EPI: 0 = relu(actA + d) -> C   (K == N, RELU_IN)
//      3 = d + bias -> C
//      4 = d -> C

__device__ __forceinline__ void mma_bf16(float* c, const uint32_t* a, uint32_t b0, uint32_t b1) {
    asm volatile(
        "mma.sync.aligned.m16n8k16.row.col.f32.bf16.bf16.f32 "
        "{%0,%1,%2,%3}, {%4,%5,%6,%7}, {%8,%9}, {%0,%1,%2,%3};"
        : "+f"(c[0]), "+f"(c[1]), "+f"(c[2]), "+f"(c[3])
        : "r"(a[0]), "r"(a[1]), "r"(a[2]), "r"(a[3]), "r"(b0), "r"(b1));
}

__device__ __forceinline__ void ldsm_x4(uint32_t* r, uint32_t addr) {
    asm volatile("ldmatrix.sync.aligned.m8n8.x4.shared.b16 {%0,%1,%2,%3}, [%4];"
                 : "=r"(r[0]), "=r"(r[1]), "=r"(r[2]), "=r"(r[3]) : "r"(addr));
}

__device__ __forceinline__ uint32_t smem_u32(const void* p) {
    uint32_t a;
    asm("{ .reg .u64 t; cvta.to.shared.u64 t, %1; cvt.u32.u64 %0, t; }" : "=r"(a) : "l"(p));
    return a;
}

template <int K, int N, bool RELU_IN, int EPI>
__global__ __launch_bounds__(256, 2) void mma_gemm_kernel(
    const float* __restrict__ A, const uint32_t* __restrict__ WF,
    float* __restrict__ C, const float* __restrict__ bias, int n) {
    constexpr int LDA = K + 8;
    constexpr int NT = N / 8;
    constexpr int KT = K / 16;
    constexpr int WN = N / 64;
    constexpr int WM = 8 / WN;
    constexpr int MT = 128 / (WM * 16);
    constexpr int LOFF = K * N / 2;

    extern __shared__ __align__(16) char smem[];
    __nv_bfloat16* Ah = (__nv_bfloat16*)smem;
    __nv_bfloat16* Al = Ah + 128 * LDA;

    const int tid = threadIdx.x;
    const int w = tid >> 5;
    const int lane = tid & 31;
    const int g = lane >> 2, tig = lane & 3;
    const int row0 = blockIdx.x * 128;
    const int wm = w / WN;
    const int wn = w % WN;

    constexpr int KQ = K / 4;
    for (int idx = tid; idx < 128 * KQ; idx += 256) {
        int r = idx / KQ;
        int k0 = (idx - r * KQ) * 4;
        float4 v = make_float4(0.f, 0.f, 0.f, 0.f);
        if (row0 + r < n) v = *(const float4*)(A + (size_t)(row0 + r) * K + k0);
        if (RELU_IN) {
            v.x = fmaxf(v.x, 0.f); v.y = fmaxf(v.y, 0.f);
            v.z = fmaxf(v.z, 0.f); v.w = fmaxf(v.w, 0.f);
        }
        __nv_bfloat16 h0 = __float2bfloat16(v.x), h1 = __float2bfloat16(v.y);
        __nv_bfloat16 h2 = __float2bfloat16(v.z), h3 = __float2bfloat16(v.w);
        __nv_bfloat162 hp0; hp0.x = h0; hp0.y = h1;
        __nv_bfloat162 hp1; hp1.x = h2; hp1.y = h3;
        __nv_bfloat162 lp0, lp1;
        lp0.x = __float2bfloat16(v.x - __bfloat162float(h0));
        lp0.y = __float2bfloat16(v.y - __bfloat162float(h1));
        lp1.x = __float2bfloat16(v.z - __bfloat162float(h2));
        lp1.y = __float2bfloat16(v.w - __bfloat162float(h3));
        *(uint2*)(Ah + r * LDA + k0) = make_uint2(*(uint32_t*)&hp0, *(uint32_t*)&hp1);
        *(uint2*)(Al + r * LDA + k0) = make_uint2(*(uint32_t*)&lp0, *(uint32_t*)&lp1);
    }
    __syncthreads();

    float acc[MT][8][4];
#pragma unroll
    for (int mt = 0; mt < MT; mt++)
#pragma unroll
        for (int nt = 0; nt < 8; nt++)
#pragma unroll
            for (int i = 0; i < 4; i++) acc[mt][nt][i] = 0.f;

    const uint32_t a_base =
        smem_u32(Ah) + (uint32_t)(((wm * MT * 16 + (lane & 15)) * LDA + (lane >> 4) * 8) * 2);
    const uint32_t l_base = a_base + (uint32_t)(128 * LDA * 2);

#pragma unroll
    for (int kt = 0; kt < KT; kt++) {
        uint32_t ah[MT][4], al[MT][4];
#pragma unroll
        for (int mt = 0; mt < MT; mt++) {
            uint32_t off = (uint32_t)((mt * 16 * LDA + kt * 16) * 2);
            ldsm_x4(ah[mt], a_base + off);
            ldsm_x4(al[mt], l_base + off);
        }
#pragma unroll
        for (int nt = 0; nt < 8; nt++) {
            int gnt = wn * 8 + nt;
            const uint32_t* bp = WF + ((size_t)(kt * NT + gnt) * 32 + lane) * 2;
            uint2 bh = *(const uint2*)bp;
            uint2 bl = *(const uint2*)(bp + LOFF);
#pragma unroll
            for (int mt = 0; mt < MT; mt++) {
                mma_bf16(acc[mt][nt], ah[mt], bh.x, bh.y);
                mma_bf16(acc[mt][nt], ah[mt], bl.x, bl.y);
                mma_bf16(acc[mt][nt], al[mt], bh.x, bh.y);
            }
        }
    }

#pragma unroll
    for (int mt = 0; mt < MT; mt++) {
        int rbase = wm * MT * 16 + mt * 16;
#pragma unroll
        for (int h = 0; h < 2; h++) {
            int rloc = rbase + g + h * 8;
            int row = row0 + rloc;
            if (row >= n) continue;
#pragma unroll
            for (int nt = 0; nt < 8; nt++) {
                int col = wn * 64 + nt * 8 + tig * 2;
                float d0 = acc[mt][nt][h * 2 + 0];
                float d1 = acc[mt][nt][h * 2 + 1];
                float v0, v1;
                if (EPI == 0) {
                    __nv_bfloat162 rh = *(const __nv_bfloat162*)(Ah + rloc * LDA + col);
                    __nv_bfloat162 rl = *(const __nv_bfloat162*)(Al + rloc * LDA + col);
                    float r0 = __bfloat162float(rh.x) + __bfloat162float(rl.x);
                    float r1 = __bfloat162float(rh.y) + __bfloat162float(rl.y);
                    v0 = fmaxf(r0 + d0, 0.f);
                    v1 = fmaxf(r1 + d1, 0.f);
                } else if (EPI == 3) {
                    v0 = d0 + __ldg(&bias[col]);
                    v1 = d1 + __ldg(&bias[col + 1]);
                } else {
                    v0 = d0; v1 = d1;
                }
                float2 o; o.x = v0; o.y = v1;
                *(float2*)(C + (size_t)row * N + col) = o;
            }
        }
    }
}

template <int K, int N, bool RELU_IN, int EPI>
static void launch_mma(const float* A, const uint32_t* WF, float* C, const float* bias, int n) {
    constexpr int SMEM = 2 * 128 * (K + 8) * 2;
    auto kfn = mma_gemm_kernel<K, N, RELU_IN, EPI>;
    if (SMEM > 48 * 1024)
        cudaFuncSetAttribute(kfn, cudaFuncAttributeMaxDynamicSharedMemorySize, SMEM);
    kfn<<<(n + 127) / 128, 256, SMEM>>>(A, WF, C, bias, n);
}

// --------------------------------- driver ----------------------------------

extern "C" void kernel_launch(void* const* d_in, const int* in_sizes, int n_in,
                              void* d_out, int out_size) {
    const float* x    = (const float*)d_in[0];
    const int*   ei   = (const int*)d_in[1];
    const float* g1w  = (const float*)d_in[2];
    const float* g1b  = (const float*)d_in[3];
    const float* fc2w = (const float*)d_in[4];
    const float* g3w  = (const float*)d_in[5];
    const float* g3b  = (const float*)d_in[6];
    const float* fc4w = (const float*)d_in[7];
    const float* g5w  = (const float*)d_in[8];
    const float* g5b  = (const float*)d_in[9];
    const float* fc6w = (const float*)d_in[10];

    int n = in_sizes[0] / 128;
    int E = in_sizes[1] / 2;
    const int* src = ei;
    const int* dst = ei + E;
    int nb = (n + 255) / 256;

    int *deg, *rs, *cursor, *blk, *csrc;
    float *cnrm, *bA, *bB, *bC;
    uint32_t* wf;
    cudaGetSymbolAddress((void**)&deg, g_deg);
    cudaGetSymbolAddress((void**)&rs, g_rs);
    cudaGetSymbolAddress((void**)&cursor, g_cursor);
    cudaGetSymbolAddress((void**)&blk, g_blk);
    cudaGetSymbolAddress((void**)&csrc, g_csrc);
    cudaGetSymbolAddress((void**)&cnrm, g_cnrm);
    cudaGetSymbolAddress((void**)&bA, g_bufA);
    cudaGetSymbolAddress((void**)&bB, g_bufB);
    cudaGetSymbolAddress((void**)&bC, g_bufC);
    cudaGetSymbolAddress((void**)&wf, g_wfrag);
    uint32_t* wf0 = wf;
    uint32_t* wf1 = wf + 16384;
    uint32_t* wf2 = wf + 2 * 16384;
    uint32_t* wf3 = wf + 3 * 16384;
    uint32_t* wf4 = wf + 4 * 16384;
    uint32_t* wf5 = wf + 5 * 16384;

    // ---- prep: weight fragments + CSR ----
    wprep_all_kernel<<<68, 256>>>(g1w, fc2w, g3w, fc4w, g5w, fc6w, wf);
    deg_zero_kernel<<<nb, 256>>>(deg, n);
    deg_count_kernel<<<(E + 255) / 256, 256>>>(dst, deg, E);
    scan1_kernel<<<nb, 256>>>(deg, cursor /*tmp*/, blk, n);   // cursor as tmp
    scan2_kernel<<<1, 32>>>(blk, nb);
    scan3_kernel<<<nb, 256>>>(cursor /*tmp*/, deg, blk, rs, cursor, n);
    scatter_kernel<<<(E + 255) / 256, 256>>>(src, dst, deg, cursor, csrc, cnrm, E);

    // ---- layer 1 ----
    launch_mma<128, 128, false, 4>(x, wf0, bA, nullptr, n);            // bA = x@W1
    csr_agg128_kernel<true><<<(n * 32 + 255) / 256, 256>>>(rs, deg, csrc, cnrm, g1b, bA, bB, n);
    launch_mma<128, 128, true, 0>(bB, wf1, bA, nullptr, n);            // bA = z1'

    // ---- layer 2 ----
    launch_mma<128, 64, false, 4>(bA, wf2, bB, nullptr, n);            // bB = z1'@W3
    csr_agg64_kernel<true><<<(n * 16 + 255) / 256, 256>>>(rs, deg, csrc, cnrm, g3b, bB, bC, n);
    launch_mma<64, 64, true, 0>(bC, wf3, bA, nullptr, n);              // bA = z2'

    // ---- layer 3 (aggregate first at d=64) ----
    csr_agg64_kernel<false><<<(n * 16 + 255) / 256, 256>>>(rs, deg, csrc, cnrm, nullptr, bA, bB, n);
    launch_mma<64, 128, false, 3>(bB, wf4, bC, g5b, n);                // bC = Agg@W5 + b5
    launch_mma<128, 128, true, 0>(bC, wf5, (float*)d_out, nullptr, n); // out
}